// round 3
// baseline (speedup 1.0000x reference)
#include <cuda_runtime.h>
#include <math.h>

// Problem constants
#define BATCH 16
#define TT    4096
#define INF   256
#define OUTF  256
#define HF    512
#define MTOT  (BATCH * TT)   // 65536
#define Y_ELEMS ((long long)MTOT * OUTF)   // 16,777,216

// ---------------------------------------------------------------------------
// Scratch: u / ys buffer, interleaved complex [M, H] float2 (256 MB).
// ---------------------------------------------------------------------------
__device__ float2 g_U[(size_t)MTOT * HF];
__device__ float2 g_lam[HF];
__device__ float2 g_cvec[HF];   // (gamma+1)*bh
__device__ float  g_gamma[HF];

// ---------------------------------------------------------------------------
// Prep: lambda, gamma, cvec
// ---------------------------------------------------------------------------
__global__ void prep_kernel(const float* __restrict__ nu_log,
                            const float* __restrict__ theta_log,
                            const float* __restrict__ bh_re,
                            const float* __restrict__ bh_im) {
    int h = threadIdx.x;
    if (h >= HF) return;
    float en = expf(nu_log[h]);
    float et = expf(theta_log[h]);
    float mag = expf(-en);                  // |lambda|
    float s, c;
    sincosf(et, &s, &c);
    g_lam[h] = make_float2(mag * c, mag * s);
    float gam = sqrtf(fmaxf(0.0f, 1.0f - mag * mag));
    g_gamma[h] = gam;
    g_cvec[h] = make_float2((gam + 1.0f) * bh_re[h], (gam + 1.0f) * bh_im[h]);
}

// ---------------------------------------------------------------------------
// GEMM 1: u[m,h] = gamma[h] * (X[m,:] . B_re[h,:] , X[m,:] . B_im[h,:])
// ---------------------------------------------------------------------------
#define BM1 128
#define BN1 64
#define BK1 16

__global__ __launch_bounds__(256)
void gemm_u_kernel(const float* __restrict__ X,
                   const float* __restrict__ Bre,
                   const float* __restrict__ Bim) {
    __shared__ float Xs[BK1][BM1 + 1];
    __shared__ float Brs[BK1][BN1 + 1];
    __shared__ float Bis[BK1][BN1 + 1];

    const int tid = threadIdx.x;
    const int tx = tid & 15;        // h direction: 16 groups of 4
    const int ty = tid >> 4;        // m direction: 16 groups of 8
    const int mBase = blockIdx.x * BM1;
    const int hBase = blockIdx.y * BN1;

    float accR[8][4];
    float accI[8][4];
#pragma unroll
    for (int r = 0; r < 8; r++)
#pragma unroll
        for (int c = 0; c < 4; c++) { accR[r][c] = 0.f; accI[r][c] = 0.f; }

    for (int k0 = 0; k0 < INF; k0 += BK1) {
#pragma unroll
        for (int l = tid; l < BM1 * BK1; l += 256) {
            int m = l >> 4, k = l & 15;
            Xs[k][m] = X[(size_t)(mBase + m) * INF + k0 + k];
        }
#pragma unroll
        for (int l = tid; l < BN1 * BK1; l += 256) {
            int h = l >> 4, k = l & 15;
            Brs[k][h] = Bre[(size_t)(hBase + h) * INF + k0 + k];
            Bis[k][h] = Bim[(size_t)(hBase + h) * INF + k0 + k];
        }
        __syncthreads();

#pragma unroll
        for (int k = 0; k < BK1; k++) {
            float a[8], br[4], bi[4];
#pragma unroll
            for (int r = 0; r < 8; r++) a[r] = Xs[k][ty * 8 + r];
#pragma unroll
            for (int c = 0; c < 4; c++) { br[c] = Brs[k][tx * 4 + c]; bi[c] = Bis[k][tx * 4 + c]; }
#pragma unroll
            for (int r = 0; r < 8; r++)
#pragma unroll
                for (int c = 0; c < 4; c++) {
                    accR[r][c] = fmaf(a[r], br[c], accR[r][c]);
                    accI[r][c] = fmaf(a[r], bi[c], accI[r][c]);
                }
        }
        __syncthreads();
    }

#pragma unroll
    for (int c = 0; c < 4; c++) {
        int h = hBase + tx * 4 + c;
        float g = g_gamma[h];
#pragma unroll
        for (int r = 0; r < 8; r++) {
            int m = mBase + ty * 8 + r;
            g_U[(size_t)m * HF + h] = make_float2(g * accR[r][c], g * accI[r][c]);
        }
    }
}

// ---------------------------------------------------------------------------
// Scan: one thread per (b, h). In-place u -> ys.
// h_N tail layout selected by tail size:
//   tail >= 16384 floats: planar  [Re(h_N) 16x512][Im(h_N) 16x512]
//   tail <  16384 floats: real-only [Re(h_N) 16x512]
// ---------------------------------------------------------------------------
__global__ __launch_bounds__(256)
void scan_kernel(float* __restrict__ out_hN, int tail_floats) {
    int g = blockIdx.x * blockDim.x + threadIdx.x;   // 0..8191
    int b = g >> 9;
    int h = g & 511;
    const float2 lam = g_lam[h];
    const float2 cv = g_cvec[h];
    float hr = 0.f, hi = 0.f;
    size_t idx = ((size_t)b * TT) * HF + h;

#pragma unroll 4
    for (int t = 0; t < TT; t++) {
        float2 v = g_U[idx];
        float vr = v.x + cv.x;
        float vi = v.y + cv.y;
        float nr = fmaf(lam.x, hr, fmaf(-lam.y, hi, vr));
        float ni = fmaf(lam.x, hi, fmaf(lam.y, hr, vi));
        hr = nr; hi = ni;
        g_U[idx] = make_float2(hr, hi);
        idx += HF;
    }

    if (tail_floats >= 2 * BATCH * HF) {
        // planar: real plane then imag plane
        out_hN[g] = hr;
        out_hN[BATCH * HF + g] = hi;
    } else {
        // real part only
        out_hN[g] = hr;
    }
}

// ---------------------------------------------------------------------------
// GEMM 2: Y[m,o] = sum_h (ysRe*CRe - ysIm*CIm) + sum_i X*D + bias[o]
// ---------------------------------------------------------------------------
#define BM2 128
#define BN2 64

__global__ __launch_bounds__(256)
void gemm_y_kernel(const float* __restrict__ X,
                   const float* __restrict__ Cre,
                   const float* __restrict__ Cim,
                   const float* __restrict__ D,
                   const float* __restrict__ bias,
                   float* __restrict__ Y) {
    __shared__ float2 Us[8][BM2 + 1];
    __shared__ float  Crs[8][BN2 + 1];
    __shared__ float  Cis[8][BN2 + 1];
    __shared__ float  Xs[16][BM2 + 1];
    __shared__ float  Ds[16][BN2 + 1];

    const int tid = threadIdx.x;
    const int tx = tid & 15;
    const int ty = tid >> 4;
    const int mBase = blockIdx.x * BM2;
    const int oBase = blockIdx.y * BN2;

    float acc[8][4];
#pragma unroll
    for (int r = 0; r < 8; r++)
#pragma unroll
        for (int c = 0; c < 4; c++) acc[r][c] = 0.f;

    // ---- phase 1: complex part over H ----
    for (int k0 = 0; k0 < HF; k0 += 8) {
#pragma unroll
        for (int l = tid; l < BM2 * 8; l += 256) {
            int m = l >> 3, k = l & 7;
            Us[k][m] = g_U[(size_t)(mBase + m) * HF + k0 + k];
        }
#pragma unroll
        for (int l = tid; l < BN2 * 8; l += 256) {
            int o = l >> 3, k = l & 7;
            Crs[k][o] = Cre[(size_t)(oBase + o) * HF + k0 + k];
            Cis[k][o] = Cim[(size_t)(oBase + o) * HF + k0 + k];
        }
        __syncthreads();

#pragma unroll
        for (int k = 0; k < 8; k++) {
            float2 a[8];
            float cr[4], ci[4];
#pragma unroll
            for (int r = 0; r < 8; r++) a[r] = Us[k][ty * 8 + r];
#pragma unroll
            for (int c = 0; c < 4; c++) { cr[c] = Crs[k][tx * 4 + c]; ci[c] = Cis[k][tx * 4 + c]; }
#pragma unroll
            for (int r = 0; r < 8; r++)
#pragma unroll
                for (int c = 0; c < 4; c++) {
                    acc[r][c] = fmaf(a[r].x, cr[c], acc[r][c]);
                    acc[r][c] = fmaf(-a[r].y, ci[c], acc[r][c]);
                }
        }
        __syncthreads();
    }

    // ---- phase 2: D part over IN ----
    for (int k0 = 0; k0 < INF; k0 += 16) {
#pragma unroll
        for (int l = tid; l < BM2 * 16; l += 256) {
            int m = l >> 4, k = l & 15;
            Xs[k][m] = X[(size_t)(mBase + m) * INF + k0 + k];
        }
#pragma unroll
        for (int l = tid; l < BN2 * 16; l += 256) {
            int o = l >> 4, k = l & 15;
            Ds[k][o] = D[(size_t)(oBase + o) * INF + k0 + k];
        }
        __syncthreads();

#pragma unroll
        for (int k = 0; k < 16; k++) {
            float a[8], d[4];
#pragma unroll
            for (int r = 0; r < 8; r++) a[r] = Xs[k][ty * 8 + r];
#pragma unroll
            for (int c = 0; c < 4; c++) d[c] = Ds[k][tx * 4 + c];
#pragma unroll
            for (int r = 0; r < 8; r++)
#pragma unroll
                for (int c = 0; c < 4; c++)
                    acc[r][c] = fmaf(a[r], d[c], acc[r][c]);
        }
        __syncthreads();
    }

    // ---- epilogue ----
#pragma unroll
    for (int c = 0; c < 4; c++) {
        int o = oBase + tx * 4 + c;
        float bs = bias[o];
#pragma unroll
        for (int r = 0; r < 8; r++) {
            int m = mBase + ty * 8 + r;
            Y[(size_t)m * OUTF + o] = acc[r][c] + bs;
        }
    }
}

// ---------------------------------------------------------------------------
// Launch
// ---------------------------------------------------------------------------
extern "C" void kernel_launch(void* const* d_in, const int* in_sizes, int n_in,
                              void* d_out, int out_size) {
    const float* X      = (const float*)d_in[0];
    const float* nu_log = (const float*)d_in[1];
    const float* th_log = (const float*)d_in[2];
    const float* Bre    = (const float*)d_in[3];
    const float* Bim    = (const float*)d_in[4];
    const float* Cre    = (const float*)d_in[5];
    const float* Cim    = (const float*)d_in[6];
    const float* D      = (const float*)d_in[7];
    const float* bh_re  = (const float*)d_in[8];
    const float* bh_im  = (const float*)d_in[9];
    const float* bias   = (const float*)d_in[10];

    float* Y = (float*)d_out;
    float* out_hN = Y + Y_ELEMS;
    int tail_floats = (int)((long long)out_size - Y_ELEMS);

    prep_kernel<<<1, HF>>>(nu_log, th_log, bh_re, bh_im);

    dim3 g1(MTOT / BM1, HF / BN1);     // (512, 8)
    gemm_u_kernel<<<g1, 256>>>(X, Bre, Bim);

    scan_kernel<<<(BATCH * HF) / 256, 256>>>(out_hN, tail_floats);

    dim3 g2(MTOT / BM2, OUTF / BN2);   // (512, 4)
    gemm_y_kernel<<<g2, 256>>>(X, Cre, Cim, D, bias, Y);
}

// round 5
// speedup vs baseline: 3.0638x; 3.0638x over previous
#include <cuda_runtime.h>
#include <cuda_bf16.h>
#include <math.h>
#include <stdint.h>

// Problem constants
#define BATCH 16
#define TT    4096
#define INF   256
#define OUTF  256
#define HF    512
#define MTOT  (BATCH * TT)              // 65536
#define K2    1280                      // GEMM2 K = 512 re + 512 im + 256 X
#define Y_ELEMS ((long long)MTOT * OUTF)

// ---------------------------------------------------------------------------
// Scratch (__device__ globals; no allocation APIs)
// ---------------------------------------------------------------------------
__device__ __align__(16) float          g_URe[(size_t)MTOT * HF];   // 134 MB
__device__ __align__(16) float          g_UIm[(size_t)MTOT * HF];   // 134 MB
__device__ __align__(16) __nv_bfloat16  g_A2hi[(size_t)MTOT * K2];  // 167 MB
__device__ __align__(16) __nv_bfloat16  g_A2lo[(size_t)MTOT * K2];  // 167 MB
__device__ __align__(16) __nv_bfloat16  g_Bhi[1024 * 256];
__device__ __align__(16) __nv_bfloat16  g_Blo[1024 * 256];
__device__ __align__(16) __nv_bfloat16  g_Whi[256 * K2];
__device__ __align__(16) __nv_bfloat16  g_Wlo[256 * K2];
__device__ float2 g_lam[HF];
__device__ float2 g_cvec[HF];
__device__ float  g_gamma[HF];

// ---------------------------------------------------------------------------
// mma.sync / ldmatrix helpers (generic PTX, no 'a'-features)
// ---------------------------------------------------------------------------
__device__ __forceinline__ uint32_t smem_u32(const void* p) {
    uint32_t a;
    asm("{ .reg .u64 t; cvta.to.shared.u64 t, %1; cvt.u32.u64 %0, t; }" : "=r"(a) : "l"(p));
    return a;
}
__device__ __forceinline__ void ldsm_x4(uint32_t& r0, uint32_t& r1, uint32_t& r2, uint32_t& r3,
                                        uint32_t addr) {
    asm volatile("ldmatrix.sync.aligned.m8n8.x4.shared.b16 {%0,%1,%2,%3}, [%4];"
                 : "=r"(r0), "=r"(r1), "=r"(r2), "=r"(r3) : "r"(addr));
}
__device__ __forceinline__ void mma16816(float* c, const uint32_t* a, uint32_t b0, uint32_t b1) {
    asm volatile(
        "mma.sync.aligned.m16n8k16.row.col.f32.bf16.bf16.f32 "
        "{%0,%1,%2,%3}, {%4,%5,%6,%7}, {%8,%9}, {%0,%1,%2,%3};"
        : "+f"(c[0]), "+f"(c[1]), "+f"(c[2]), "+f"(c[3])
        : "r"(a[0]), "r"(a[1]), "r"(a[2]), "r"(a[3]), "r"(b0), "r"(b1));
}

// ---------------------------------------------------------------------------
// SMEM layout: four 128x64 bf16 tiles, row stride 144 B (padded, LDSM-conflict-free)
// ---------------------------------------------------------------------------
#define TILE_BYTES (128 * 144)          // 18432
#define S_A_HI 0
#define S_A_LO (TILE_BYTES)
#define S_B_HI (2 * TILE_BYTES)
#define S_B_LO (3 * TILE_BYTES)
#define SMEM_BYTES (4 * TILE_BYTES)     // 73728

// Load a 128x64 bf16 tile (row stride ld elems) into padded smem. 256 threads.
__device__ __forceinline__ void ld_tile(uint32_t sbase, const __nv_bfloat16* __restrict__ g,
                                        int ld, int tid) {
#pragma unroll
    for (int it = 0; it < 4; it++) {
        int u = tid + it * 256;         // 0..1023
        int r = u >> 3, j = u & 7;
        uint4 v = *reinterpret_cast<const uint4*>(g + (size_t)r * ld + j * 8);
        uint32_t a = sbase + r * 144 + j * 16;
        asm volatile("st.shared.v4.b32 [%0], {%1,%2,%3,%4};"
                     :: "r"(a), "r"(v.x), "r"(v.y), "r"(v.z), "r"(v.w));
    }
}

// ---------------------------------------------------------------------------
// Shared GEMM core: acc[2][8][4] += Asplit(128xK) . Bsplit(128xK)^T  per block
// (3-pass split bf16: hi*hi + lo*hi + hi*lo)
// ---------------------------------------------------------------------------
__device__ __forceinline__ void gemm_core(
    float acc[2][8][4],
    const __nv_bfloat16* __restrict__ Ahi, const __nv_bfloat16* __restrict__ Alo, int lda,
    const __nv_bfloat16* __restrict__ Bhi, const __nv_bfloat16* __restrict__ Blo, int ldb,
    int kChunks, uint32_t sb, int tid) {

    const int lane = tid & 31;
    const int warp = tid >> 5;
    const int wm = warp & 3;            // m strip (32 rows)
    const int wn = warp >> 2;           // n strip (64 cols)

    // ldmatrix per-thread address components
    const int a_row = wm * 32 + (lane & 15);
    const uint32_t a_coff = (uint32_t)((lane >> 4) << 4);          // (t/16)*16 B
    const int b_rowl = (lane & 7) + ((lane >> 4) << 3);            // (t%8) + (t/16)*8
    const uint32_t b_coff = (uint32_t)(((lane >> 3) & 1) << 4);    // ((t/8)%2)*16 B

    for (int kc = 0; kc < kChunks; kc++) {
        ld_tile(sb + S_A_HI, Ahi + kc * 64, lda, tid);
        ld_tile(sb + S_A_LO, Alo + kc * 64, lda, tid);
        ld_tile(sb + S_B_HI, Bhi + kc * 64, ldb, tid);
        ld_tile(sb + S_B_LO, Blo + kc * 64, ldb, tid);
        __syncthreads();

#pragma unroll
        for (int k16 = 0; k16 < 4; k16++) {
            const uint32_t koff = (uint32_t)(k16 * 32);
            uint32_t ah[2][4], al[2][4], bf[4][4];

            ldsm_x4(ah[0][0], ah[0][1], ah[0][2], ah[0][3],
                    sb + S_A_HI + (uint32_t)a_row * 144 + koff + a_coff);
            ldsm_x4(ah[1][0], ah[1][1], ah[1][2], ah[1][3],
                    sb + S_A_HI + (uint32_t)(a_row + 16) * 144 + koff + a_coff);
            ldsm_x4(al[0][0], al[0][1], al[0][2], al[0][3],
                    sb + S_A_LO + (uint32_t)a_row * 144 + koff + a_coff);
            ldsm_x4(al[1][0], al[1][1], al[1][2], al[1][3],
                    sb + S_A_LO + (uint32_t)(a_row + 16) * 144 + koff + a_coff);

#pragma unroll
            for (int ng = 0; ng < 4; ng++)
                ldsm_x4(bf[ng][0], bf[ng][1], bf[ng][2], bf[ng][3],
                        sb + S_B_HI + (uint32_t)(wn * 64 + ng * 16 + b_rowl) * 144 + koff + b_coff);

            // pass 1: hi*hi ; pass 2: lo*hi
#pragma unroll
            for (int ng = 0; ng < 4; ng++) {
                mma16816(acc[0][2 * ng],     ah[0], bf[ng][0], bf[ng][1]);
                mma16816(acc[0][2 * ng + 1], ah[0], bf[ng][2], bf[ng][3]);
                mma16816(acc[1][2 * ng],     ah[1], bf[ng][0], bf[ng][1]);
                mma16816(acc[1][2 * ng + 1], ah[1], bf[ng][2], bf[ng][3]);
                mma16816(acc[0][2 * ng],     al[0], bf[ng][0], bf[ng][1]);
                mma16816(acc[0][2 * ng + 1], al[0], bf[ng][2], bf[ng][3]);
                mma16816(acc[1][2 * ng],     al[1], bf[ng][0], bf[ng][1]);
                mma16816(acc[1][2 * ng + 1], al[1], bf[ng][2], bf[ng][3]);
            }

            // pass 3: hi*lo (reuse bf regs)
#pragma unroll
            for (int ng = 0; ng < 4; ng++)
                ldsm_x4(bf[ng][0], bf[ng][1], bf[ng][2], bf[ng][3],
                        sb + S_B_LO + (uint32_t)(wn * 64 + ng * 16 + b_rowl) * 144 + koff + b_coff);
#pragma unroll
            for (int ng = 0; ng < 4; ng++) {
                mma16816(acc[0][2 * ng],     ah[0], bf[ng][0], bf[ng][1]);
                mma16816(acc[0][2 * ng + 1], ah[0], bf[ng][2], bf[ng][3]);
                mma16816(acc[1][2 * ng],     ah[1], bf[ng][0], bf[ng][1]);
                mma16816(acc[1][2 * ng + 1], ah[1], bf[ng][2], bf[ng][3]);
            }
        }
        __syncthreads();
    }
}

// ---------------------------------------------------------------------------
// Prep kernels
// ---------------------------------------------------------------------------
__global__ void prep_kernel(const float* __restrict__ nu_log,
                            const float* __restrict__ theta_log,
                            const float* __restrict__ bh_re,
                            const float* __restrict__ bh_im) {
    int h = threadIdx.x;
    if (h >= HF) return;
    float en = expf(nu_log[h]);
    float et = expf(theta_log[h]);
    float mag = expf(-en);
    float s, c;
    sincosf(et, &s, &c);
    g_lam[h] = make_float2(mag * c, mag * s);
    float gam = sqrtf(fmaxf(0.0f, 1.0f - mag * mag));
    g_gamma[h] = gam;
    g_cvec[h] = make_float2((gam + 1.0f) * bh_re[h], (gam + 1.0f) * bh_im[h]);
}

__device__ __forceinline__ void split_bf16(float x, __nv_bfloat16& h, __nv_bfloat16& l) {
    h = __float2bfloat16(x);
    l = __float2bfloat16(x - __bfloat162float(h));
}

// Weights: Bcat = [Bre; Bim] (1024x256), Wcat = [Cre | -Cim | D] (256x1280)
__global__ void wprep_kernel(const float* __restrict__ Bre, const float* __restrict__ Bim,
                             const float* __restrict__ Cre, const float* __restrict__ Cim,
                             const float* __restrict__ D) {
    int n = blockIdx.x * blockDim.x + threadIdx.x;
    if (n < 1024 * 256) {
        int r = n >> 8, i = n & 255;
        float v = (r < 512) ? Bre[r * 256 + i] : Bim[(r - 512) * 256 + i];
        __nv_bfloat16 h, l; split_bf16(v, h, l);
        g_Bhi[n] = h; g_Blo[n] = l;
    } else {
        int n2 = n - 1024 * 256;
        if (n2 < 256 * K2) {
            int o = n2 / K2, k = n2 % K2;
            float v;
            if (k < 512)       v = Cre[o * 512 + k];
            else if (k < 1024) v = -Cim[o * 512 + (k - 512)];
            else               v = D[o * 256 + (k - 1024)];
            __nv_bfloat16 h, l; split_bf16(v, h, l);
            g_Whi[n2] = h; g_Wlo[n2] = l;
        }
    }
}

// X -> split bf16 into A2 cols [1024..1279]
__global__ void convx_kernel(const float* __restrict__ X) {
    long long g = (long long)blockIdx.x * blockDim.x + threadIdx.x;
    if (g >= (long long)MTOT * INF) return;
    int m = (int)(g >> 8), i = (int)(g & 255);
    __nv_bfloat16 h, l; split_bf16(X[g], h, l);
    size_t idx = (size_t)m * K2 + 1024 + i;
    g_A2hi[idx] = h; g_A2lo[idx] = l;
}

// ---------------------------------------------------------------------------
// GEMM1: U[m, 0..1023] = gamma * (Xsplit . BcatT), fp32 planar out (URe|UIm)
// ---------------------------------------------------------------------------
__global__ __launch_bounds__(256, 2) void gemm1_kernel() {
    extern __shared__ char smem[];
    uint32_t sb = smem_u32(smem);
    const int tid = threadIdx.x;
    const int lane = tid & 31;
    const int warp = tid >> 5;
    const int wm = warp & 3, wn = warp >> 2;
    const int mBase = blockIdx.y * 128;
    const int colBase = blockIdx.x * 128;   // 0..895

    float acc[2][8][4];
#pragma unroll
    for (int a = 0; a < 2; a++)
#pragma unroll
        for (int b = 0; b < 8; b++)
#pragma unroll
            for (int c = 0; c < 4; c++) acc[a][b][c] = 0.f;

    gemm_core(acc,
              g_A2hi + (size_t)mBase * K2 + 1024,
              g_A2lo + (size_t)mBase * K2 + 1024, K2,
              g_Bhi + (size_t)colBase * 256,
              g_Blo + (size_t)colBase * 256, 256,
              4, sb, tid);

    // epilogue: gamma scale, route to URe / UIm
    float* dst = (colBase < 512) ? g_URe : g_UIm;
#pragma unroll
    for (int nt = 0; nt < 8; nt++) {
        int col = colBase + wn * 64 + nt * 8 + (lane & 3) * 2;
        int h = col & 511;
        float g0 = g_gamma[h], g1 = g_gamma[h + 1];
#pragma unroll
        for (int mt = 0; mt < 2; mt++) {
            float* c = acc[mt][nt];
            int m0 = mBase + wm * 32 + mt * 16 + (lane >> 2);
            *reinterpret_cast<float2*>(&dst[(size_t)m0 * 512 + h]) =
                make_float2(c[0] * g0, c[1] * g1);
            *reinterpret_cast<float2*>(&dst[(size_t)(m0 + 8) * 512 + h]) =
                make_float2(c[2] * g0, c[3] * g1);
        }
    }
}

// ---------------------------------------------------------------------------
// Scan: chunked-parallel (|lambda| <= e^-1; 64-step warmup). 8 chunks of 512.
// Emits ys split-bf16 into A2 cols [0..1023]; writes h_N planar.
// ---------------------------------------------------------------------------
#define SCH   512
#define SWARM 64
__global__ __launch_bounds__(256) void scan_kernel(float* __restrict__ out_hN) {
    int g = blockIdx.x * blockDim.x + threadIdx.x;   // 0..65535
    int h = g & 511;
    int ch = (g >> 9) & 7;
    int b = g >> 12;
    const float2 lam = g_lam[h];
    const float2 cv = g_cvec[h];
    float hr = 0.f, hi = 0.f;
    const int t0 = ch * SCH;
    const int tw = (ch == 0) ? 0 : t0 - SWARM;
    size_t ub = ((size_t)b * TT + tw) * HF + h;
    for (int t = tw; t < t0; t++) {
        float vr = g_URe[ub] + cv.x;
        float vi = g_UIm[ub] + cv.y;
        float nr = fmaf(lam.x, hr, fmaf(-lam.y, hi, vr));
        float ni = fmaf(lam.x, hi, fmaf(lam.y, hr, vi));
        hr = nr; hi = ni; ub += HF;
    }
    size_t arow = ((size_t)b * TT + t0) * K2;
    for (int t = 0; t < SCH; t++) {
        float vr = g_URe[ub] + cv.x;
        float vi = g_UIm[ub] + cv.y;
        float nr = fmaf(lam.x, hr, fmaf(-lam.y, hi, vr));
        float ni = fmaf(lam.x, hi, fmaf(lam.y, hr, vi));
        hr = nr; hi = ni; ub += HF;
        __nv_bfloat16 rh, rl, ih, il;
        split_bf16(hr, rh, rl);
        split_bf16(hi, ih, il);
        g_A2hi[arow + h] = rh;       g_A2lo[arow + h] = rl;
        g_A2hi[arow + 512 + h] = ih; g_A2lo[arow + 512 + h] = il;
        arow += K2;
    }
    if (ch == 7) {
        int g2 = b * 512 + h;
        out_hN[g2] = hr;                 // Re plane
        out_hN[BATCH * HF + g2] = hi;    // Im plane
    }
}

// ---------------------------------------------------------------------------
// GEMM2: Y[m, 256] = A2split . WcatT + bias   (K = 1280)
// ---------------------------------------------------------------------------
__global__ __launch_bounds__(256, 2) void gemm2_kernel(const float* __restrict__ bias,
                                                       float* __restrict__ Y) {
    extern __shared__ char smem[];
    uint32_t sb = smem_u32(smem);
    const int tid = threadIdx.x;
    const int lane = tid & 31;
    const int warp = tid >> 5;
    const int wm = warp & 3, wn = warp >> 2;
    const int mBase = blockIdx.y * 128;
    const int colBase = blockIdx.x * 128;   // 0 or 128

    float acc[2][8][4];
#pragma unroll
    for (int a = 0; a < 2; a++)
#pragma unroll
        for (int b = 0; b < 8; b++)
#pragma unroll
            for (int c = 0; c < 4; c++) acc[a][b][c] = 0.f;

    gemm_core(acc,
              g_A2hi + (size_t)mBase * K2,
              g_A2lo + (size_t)mBase * K2, K2,
              g_Whi + (size_t)colBase * K2,
              g_Wlo + (size_t)colBase * K2, K2,
              20, sb, tid);

    // epilogue: + bias, store Y
#pragma unroll
    for (int nt = 0; nt < 8; nt++) {
        int col = colBase + wn * 64 + nt * 8 + (lane & 3) * 2;
        float b0 = bias[col], b1 = bias[col + 1];
#pragma unroll
        for (int mt = 0; mt < 2; mt++) {
            float* c = acc[mt][nt];
            int m0 = mBase + wm * 32 + mt * 16 + (lane >> 2);
            *reinterpret_cast<float2*>(&Y[(size_t)m0 * OUTF + col]) =
                make_float2(c[0] + b0, c[1] + b1);
            *reinterpret_cast<float2*>(&Y[(size_t)(m0 + 8) * OUTF + col]) =
                make_float2(c[2] + b0, c[3] + b1);
        }
    }
}

// ---------------------------------------------------------------------------
// Launch
// ---------------------------------------------------------------------------
extern "C" void kernel_launch(void* const* d_in, const int* in_sizes, int n_in,
                              void* d_out, int out_size) {
    const float* X      = (const float*)d_in[0];
    const float* nu_log = (const float*)d_in[1];
    const float* th_log = (const float*)d_in[2];
    const float* Bre    = (const float*)d_in[3];
    const float* Bim    = (const float*)d_in[4];
    const float* Cre    = (const float*)d_in[5];
    const float* Cim    = (const float*)d_in[6];
    const float* D      = (const float*)d_in[7];
    const float* bh_re  = (const float*)d_in[8];
    const float* bh_im  = (const float*)d_in[9];
    const float* bias   = (const float*)d_in[10];

    float* Y = (float*)d_out;
    float* out_hN = Y + Y_ELEMS;

    static int smem_set = 0;
    if (!smem_set) {
        cudaFuncSetAttribute(gemm1_kernel, cudaFuncAttributeMaxDynamicSharedMemorySize, SMEM_BYTES);
        cudaFuncSetAttribute(gemm2_kernel, cudaFuncAttributeMaxDynamicSharedMemorySize, SMEM_BYTES);
        smem_set = 1;
    }

    prep_kernel<<<1, HF>>>(nu_log, th_log, bh_re, bh_im);

    int wtot = 1024 * 256 + 256 * K2;
    wprep_kernel<<<(wtot + 255) / 256, 256>>>(Bre, Bim, Cre, Cim, D);

    convx_kernel<<<(MTOT * INF) / 256, 256>>>(X);

    dim3 g1(8, MTOT / 128);     // n-blocks fastest for A-tile L2 reuse
    gemm1_kernel<<<g1, 256, SMEM_BYTES>>>();

    scan_kernel<<<(BATCH * 8 * HF) / 256, 256>>>(out_hN);

    dim3 g2(2, MTOT / 128);
    gemm2_kernel<<<g2, 256, SMEM_BYTES>>>(bias, Y);
}

// round 6
// speedup vs baseline: 3.7164x; 1.2130x over previous
#include <cuda_runtime.h>
#include <cuda_bf16.h>
#include <math.h>
#include <stdint.h>

// Problem constants
#define BATCH 16
#define TT    4096
#define INF   256
#define OUTF  256
#define HF    512
#define MTOT  (BATCH * TT)              // 65536
#define K2    1280                      // GEMM2 K = 512 re + 512 im + 256 X
#define Y_ELEMS ((long long)MTOT * OUTF)

// ---------------------------------------------------------------------------
// Scratch (__device__ globals; no allocation APIs)
// ---------------------------------------------------------------------------
__device__ __align__(16) float          g_URe[(size_t)MTOT * HF];
__device__ __align__(16) float          g_UIm[(size_t)MTOT * HF];
__device__ __align__(16) __nv_bfloat16  g_A2hi[(size_t)MTOT * K2];
__device__ __align__(16) __nv_bfloat16  g_A2lo[(size_t)MTOT * K2];
__device__ __align__(16) __nv_bfloat16  g_Bhi[1024 * 256];
__device__ __align__(16) __nv_bfloat16  g_Blo[1024 * 256];
__device__ __align__(16) __nv_bfloat16  g_Whi[256 * K2];
__device__ __align__(16) __nv_bfloat16  g_Wlo[256 * K2];
__device__ float2 g_lam[HF];
__device__ float2 g_cvec[HF];
__device__ float  g_gamma[HF];

// ---------------------------------------------------------------------------
// PTX helpers (generic PTX only; no sm_103a-only features)
// ---------------------------------------------------------------------------
__device__ __forceinline__ uint32_t smem_u32(const void* p) {
    uint32_t a;
    asm("{ .reg .u64 t; cvta.to.shared.u64 t, %1; cvt.u32.u64 %0, t; }" : "=r"(a) : "l"(p));
    return a;
}
__device__ __forceinline__ void ldsm_x4(uint32_t& r0, uint32_t& r1, uint32_t& r2, uint32_t& r3,
                                        uint32_t addr) {
    asm volatile("ldmatrix.sync.aligned.m8n8.x4.shared.b16 {%0,%1,%2,%3}, [%4];"
                 : "=r"(r0), "=r"(r1), "=r"(r2), "=r"(r3) : "r"(addr));
}
__device__ __forceinline__ void mma16816(float* c, const uint32_t* a, uint32_t b0, uint32_t b1) {
    asm volatile(
        "mma.sync.aligned.m16n8k16.row.col.f32.bf16.bf16.f32 "
        "{%0,%1,%2,%3}, {%4,%5,%6,%7}, {%8,%9}, {%0,%1,%2,%3};"
        : "+f"(c[0]), "+f"(c[1]), "+f"(c[2]), "+f"(c[3])
        : "r"(a[0]), "r"(a[1]), "r"(a[2]), "r"(a[3]), "r"(b0), "r"(b1));
}
__device__ __forceinline__ void cp_async16(uint32_t sdst, const void* gsrc) {
    asm volatile("cp.async.cg.shared.global [%0], [%1], 16;"
                 :: "r"(sdst), "l"(__cvta_generic_to_global(gsrc)) : "memory");
}
#define CP_COMMIT()  asm volatile("cp.async.commit_group;" ::: "memory")
#define CP_WAIT(n)   asm volatile("cp.async.wait_group %0;" :: "n"(n) : "memory")

// ---------------------------------------------------------------------------
// SMEM: 2 stages x 4 tiles of 128 rows x 32 bf16, row stride 80 B
// (80 = 5*16: cp.async-16 aligned; r*20 mod 32 distinct for r in 0..7 =>
//  ldmatrix conflict-free)
// ---------------------------------------------------------------------------
#define TSTR   80
#define TILE_B (128 * TSTR)             // 10240
#define S_A_HI 0
#define S_A_LO (TILE_B)
#define S_B_HI (2 * TILE_B)
#define S_B_LO (3 * TILE_B)
#define STAGE_B (4 * TILE_B)            // 40960
#define SMEM_BYTES (2 * STAGE_B)        // 81920

// Async-load one 128x32 bf16 tile (row stride ld elems). 256 threads, 2 iters.
__device__ __forceinline__ void ld_tile_async(uint32_t sbase, const __nv_bfloat16* __restrict__ g,
                                              int ld, int tid) {
#pragma unroll
    for (int it = 0; it < 2; it++) {
        int u = tid + it * 256;         // 0..511
        int r = u >> 2, j = u & 3;
        cp_async16(sbase + r * TSTR + j * 16, g + (size_t)r * ld + j * 8);
    }
}

__device__ __forceinline__ void ld_stage(uint32_t sb,
                                         const __nv_bfloat16* Ahi, const __nv_bfloat16* Alo, int lda,
                                         const __nv_bfloat16* Bhi, const __nv_bfloat16* Blo, int ldb,
                                         int kc, int tid) {
    ld_tile_async(sb + S_A_HI, Ahi + kc * 32, lda, tid);
    ld_tile_async(sb + S_A_LO, Alo + kc * 32, lda, tid);
    ld_tile_async(sb + S_B_HI, Bhi + kc * 32, ldb, tid);
    ld_tile_async(sb + S_B_LO, Blo + kc * 32, ldb, tid);
}

// Compute one BK=32 chunk (2 k16 steps) from stage at sb.
__device__ __forceinline__ void compute_chunk(float acc[2][8][4], uint32_t sb,
                                              int lane, int wm, int wn) {
    const int a_row = wm * 32 + (lane & 15);
    const uint32_t a_coff = (uint32_t)((lane >> 4) << 4);
    const int b_rowl = (lane & 7) + ((lane >> 4) << 3);
    const uint32_t b_coff = (uint32_t)(((lane >> 3) & 1) << 4);

#pragma unroll
    for (int k16 = 0; k16 < 2; k16++) {
        const uint32_t koff = (uint32_t)(k16 * 32);
        uint32_t ah[2][4], al[2][4], bf[4][4];

        ldsm_x4(ah[0][0], ah[0][1], ah[0][2], ah[0][3],
                sb + S_A_HI + (uint32_t)a_row * TSTR + koff + a_coff);
        ldsm_x4(ah[1][0], ah[1][1], ah[1][2], ah[1][3],
                sb + S_A_HI + (uint32_t)(a_row + 16) * TSTR + koff + a_coff);
        ldsm_x4(al[0][0], al[0][1], al[0][2], al[0][3],
                sb + S_A_LO + (uint32_t)a_row * TSTR + koff + a_coff);
        ldsm_x4(al[1][0], al[1][1], al[1][2], al[1][3],
                sb + S_A_LO + (uint32_t)(a_row + 16) * TSTR + koff + a_coff);

#pragma unroll
        for (int ng = 0; ng < 4; ng++)
            ldsm_x4(bf[ng][0], bf[ng][1], bf[ng][2], bf[ng][3],
                    sb + S_B_HI + (uint32_t)(wn * 64 + ng * 16 + b_rowl) * TSTR + koff + b_coff);

        // pass 1: hi*hi ; pass 2: lo*hi
#pragma unroll
        for (int ng = 0; ng < 4; ng++) {
            mma16816(acc[0][2 * ng],     ah[0], bf[ng][0], bf[ng][1]);
            mma16816(acc[0][2 * ng + 1], ah[0], bf[ng][2], bf[ng][3]);
            mma16816(acc[1][2 * ng],     ah[1], bf[ng][0], bf[ng][1]);
            mma16816(acc[1][2 * ng + 1], ah[1], bf[ng][2], bf[ng][3]);
            mma16816(acc[0][2 * ng],     al[0], bf[ng][0], bf[ng][1]);
            mma16816(acc[0][2 * ng + 1], al[0], bf[ng][2], bf[ng][3]);
            mma16816(acc[1][2 * ng],     al[1], bf[ng][0], bf[ng][1]);
            mma16816(acc[1][2 * ng + 1], al[1], bf[ng][2], bf[ng][3]);
        }
        // pass 3: hi*lo (reuse bf regs)
#pragma unroll
        for (int ng = 0; ng < 4; ng++)
            ldsm_x4(bf[ng][0], bf[ng][1], bf[ng][2], bf[ng][3],
                    sb + S_B_LO + (uint32_t)(wn * 64 + ng * 16 + b_rowl) * TSTR + koff + b_coff);
#pragma unroll
        for (int ng = 0; ng < 4; ng++) {
            mma16816(acc[0][2 * ng],     ah[0], bf[ng][0], bf[ng][1]);
            mma16816(acc[0][2 * ng + 1], ah[0], bf[ng][2], bf[ng][3]);
            mma16816(acc[1][2 * ng],     ah[1], bf[ng][0], bf[ng][1]);
            mma16816(acc[1][2 * ng + 1], ah[1], bf[ng][2], bf[ng][3]);
        }
    }
}

// Double-buffered GEMM core.
__device__ __forceinline__ void gemm_core(
    float acc[2][8][4],
    const __nv_bfloat16* __restrict__ Ahi, const __nv_bfloat16* __restrict__ Alo, int lda,
    const __nv_bfloat16* __restrict__ Bhi, const __nv_bfloat16* __restrict__ Blo, int ldb,
    int kChunks, uint32_t sb, int tid) {

    const int lane = tid & 31;
    const int warp = tid >> 5;
    const int wm = warp & 3, wn = warp >> 2;

    ld_stage(sb, Ahi, Alo, lda, Bhi, Blo, ldb, 0, tid);
    CP_COMMIT();

    for (int kc = 0; kc < kChunks; kc++) {
        if (kc + 1 < kChunks) {
            ld_stage(sb + ((kc + 1) & 1) * STAGE_B, Ahi, Alo, lda, Bhi, Blo, ldb, kc + 1, tid);
            CP_COMMIT();
            CP_WAIT(1);
        } else {
            CP_WAIT(0);
        }
        __syncthreads();
        compute_chunk(acc, sb + (kc & 1) * STAGE_B, lane, wm, wn);
        __syncthreads();
    }
}

// ---------------------------------------------------------------------------
// Prep kernels
// ---------------------------------------------------------------------------
__global__ void prep_kernel(const float* __restrict__ nu_log,
                            const float* __restrict__ theta_log,
                            const float* __restrict__ bh_re,
                            const float* __restrict__ bh_im) {
    int h = threadIdx.x;
    if (h >= HF) return;
    float en = expf(nu_log[h]);
    float et = expf(theta_log[h]);
    float mag = expf(-en);
    float s, c;
    sincosf(et, &s, &c);
    g_lam[h] = make_float2(mag * c, mag * s);
    float gam = sqrtf(fmaxf(0.0f, 1.0f - mag * mag));
    g_gamma[h] = gam;
    g_cvec[h] = make_float2((gam + 1.0f) * bh_re[h], (gam + 1.0f) * bh_im[h]);
}

__device__ __forceinline__ void split_bf16(float x, __nv_bfloat16& h, __nv_bfloat16& l) {
    h = __float2bfloat16(x);
    l = __float2bfloat16(x - __bfloat162float(h));
}

// Weights: Bcat = [Bre; Bim] (1024x256), Wcat = [Cre | -Cim | D] (256x1280)
__global__ void wprep_kernel(const float* __restrict__ Bre, const float* __restrict__ Bim,
                             const float* __restrict__ Cre, const float* __restrict__ Cim,
                             const float* __restrict__ D) {
    int n = blockIdx.x * blockDim.x + threadIdx.x;
    if (n < 1024 * 256) {
        int r = n >> 8, i = n & 255;
        float v = (r < 512) ? Bre[r * 256 + i] : Bim[(r - 512) * 256 + i];
        __nv_bfloat16 h, l; split_bf16(v, h, l);
        g_Bhi[n] = h; g_Blo[n] = l;
    } else {
        int n2 = n - 1024 * 256;
        if (n2 < 256 * K2) {
            int o = n2 / K2, k = n2 % K2;
            float v;
            if (k < 512)       v = Cre[o * 512 + k];
            else if (k < 1024) v = -Cim[o * 512 + (k - 512)];
            else               v = D[o * 256 + (k - 1024)];
            __nv_bfloat16 h, l; split_bf16(v, h, l);
            g_Whi[n2] = h; g_Wlo[n2] = l;
        }
    }
}

// X -> split bf16 into A2 cols [1024..1279] (float4 in, bf16x2 out)
__global__ void convx_kernel(const float* __restrict__ X) {
    long long g4 = (long long)blockIdx.x * blockDim.x + threadIdx.x;
    if (g4 >= (long long)MTOT * INF / 4) return;
    int m = (int)(g4 >> 6), i = (int)(g4 & 63) * 4;
    float4 v = *reinterpret_cast<const float4*>(X + (size_t)m * INF + i);
    __nv_bfloat16 h0, l0, h1, l1, h2, l2, h3, l3;
    split_bf16(v.x, h0, l0); split_bf16(v.y, h1, l1);
    split_bf16(v.z, h2, l2); split_bf16(v.w, h3, l3);
    size_t idx = (size_t)m * K2 + 1024 + i;
    *reinterpret_cast<__nv_bfloat162*>(g_A2hi + idx)     = __nv_bfloat162(h0, h1);
    *reinterpret_cast<__nv_bfloat162*>(g_A2hi + idx + 2) = __nv_bfloat162(h2, h3);
    *reinterpret_cast<__nv_bfloat162*>(g_A2lo + idx)     = __nv_bfloat162(l0, l1);
    *reinterpret_cast<__nv_bfloat162*>(g_A2lo + idx + 2) = __nv_bfloat162(l2, l3);
}

// ---------------------------------------------------------------------------
// GEMM1: U[m, 0..1023] = gamma * (Xsplit . BcatT), fp32 planar out (URe|UIm)
// ---------------------------------------------------------------------------
__global__ __launch_bounds__(256, 2) void gemm1_kernel() {
    extern __shared__ char smem[];
    uint32_t sb = smem_u32(smem);
    const int tid = threadIdx.x;
    const int lane = tid & 31;
    const int warp = tid >> 5;
    const int wm = warp & 3, wn = warp >> 2;
    const int mBase = blockIdx.y * 128;
    const int colBase = blockIdx.x * 128;

    float acc[2][8][4];
#pragma unroll
    for (int a = 0; a < 2; a++)
#pragma unroll
        for (int b = 0; b < 8; b++)
#pragma unroll
            for (int c = 0; c < 4; c++) acc[a][b][c] = 0.f;

    gemm_core(acc,
              g_A2hi + (size_t)mBase * K2 + 1024,
              g_A2lo + (size_t)mBase * K2 + 1024, K2,
              g_Bhi + (size_t)colBase * 256,
              g_Blo + (size_t)colBase * 256, 256,
              8, sb, tid);

    float* dst = (colBase < 512) ? g_URe : g_UIm;
#pragma unroll
    for (int nt = 0; nt < 8; nt++) {
        int col = colBase + wn * 64 + nt * 8 + (lane & 3) * 2;
        int h = col & 511;
        float g0 = g_gamma[h], g1 = g_gamma[h + 1];
#pragma unroll
        for (int mt = 0; mt < 2; mt++) {
            float* c = acc[mt][nt];
            int m0 = mBase + wm * 32 + mt * 16 + (lane >> 2);
            *reinterpret_cast<float2*>(&dst[(size_t)m0 * 512 + h]) =
                make_float2(c[0] * g0, c[1] * g1);
            *reinterpret_cast<float2*>(&dst[(size_t)(m0 + 8) * 512 + h]) =
                make_float2(c[2] * g0, c[3] * g1);
        }
    }
}

// ---------------------------------------------------------------------------
// Scan: chunked-parallel, 16 chunks of 256 (+64 warmup; lambda^64 ~ 1.6e-28).
// Emits ys split-bf16 into A2 cols [0..1023]; writes h_N planar.
// ---------------------------------------------------------------------------
#define SCH   256
#define SWARM 64
__global__ __launch_bounds__(256) void scan_kernel(float* __restrict__ out_hN) {
    int g = blockIdx.x * blockDim.x + threadIdx.x;   // 0..131071
    int h = g & 511;
    int ch = (g >> 9) & 15;
    int b = g >> 13;
    const float2 lam = g_lam[h];
    const float2 cv = g_cvec[h];
    float hr = 0.f, hi = 0.f;
    const int t0 = ch * SCH;
    const int tw = (ch == 0) ? 0 : t0 - SWARM;
    size_t ub = ((size_t)b * TT + tw) * HF + h;
    for (int t = tw; t < t0; t++) {
        float vr = g_URe[ub] + cv.x;
        float vi = g_UIm[ub] + cv.y;
        float nr = fmaf(lam.x, hr, fmaf(-lam.y, hi, vr));
        float ni = fmaf(lam.x, hi, fmaf(lam.y, hr, vi));
        hr = nr; hi = ni; ub += HF;
    }
    size_t arow = ((size_t)b * TT + t0) * K2;
    for (int t = 0; t < SCH; t++) {
        float vr = g_URe[ub] + cv.x;
        float vi = g_UIm[ub] + cv.y;
        float nr = fmaf(lam.x, hr, fmaf(-lam.y, hi, vr));
        float ni = fmaf(lam.x, hi, fmaf(lam.y, hr, vi));
        hr = nr; hi = ni; ub += HF;
        __nv_bfloat16 rh, rl, ih, il;
        split_bf16(hr, rh, rl);
        split_bf16(hi, ih, il);
        g_A2hi[arow + h] = rh;       g_A2lo[arow + h] = rl;
        g_A2hi[arow + 512 + h] = ih; g_A2lo[arow + 512 + h] = il;
        arow += K2;
    }
    if (ch == 15) {
        int g2 = b * 512 + h;
        out_hN[g2] = hr;                 // Re plane
        out_hN[BATCH * HF + g2] = hi;    // Im plane
    }
}

// ---------------------------------------------------------------------------
// GEMM2: Y[m, 256] = A2split . WcatT + bias   (K = 1280)
// ---------------------------------------------------------------------------
__global__ __launch_bounds__(256, 2) void gemm2_kernel(const float* __restrict__ bias,
                                                       float* __restrict__ Y) {
    extern __shared__ char smem[];
    uint32_t sb = smem_u32(smem);
    const int tid = threadIdx.x;
    const int lane = tid & 31;
    const int warp = tid >> 5;
    const int wm = warp & 3, wn = warp >> 2;
    const int mBase = blockIdx.y * 128;
    const int colBase = blockIdx.x * 128;

    float acc[2][8][4];
#pragma unroll
    for (int a = 0; a < 2; a++)
#pragma unroll
        for (int b = 0; b < 8; b++)
#pragma unroll
            for (int c = 0; c < 4; c++) acc[a][b][c] = 0.f;

    gemm_core(acc,
              g_A2hi + (size_t)mBase * K2,
              g_A2lo + (size_t)mBase * K2, K2,
              g_Whi + (size_t)colBase * K2,
              g_Wlo + (size_t)colBase * K2, K2,
              40, sb, tid);

#pragma unroll
    for (int nt = 0; nt < 8; nt++) {
        int col = colBase + wn * 64 + nt * 8 + (lane & 3) * 2;
        float b0 = bias[col], b1 = bias[col + 1];
#pragma unroll
        for (int mt = 0; mt < 2; mt++) {
            float* c = acc[mt][nt];
            int m0 = mBase + wm * 32 + mt * 16 + (lane >> 2);
            *reinterpret_cast<float2*>(&Y[(size_t)m0 * OUTF + col]) =
                make_float2(c[0] + b0, c[1] + b1);
            *reinterpret_cast<float2*>(&Y[(size_t)(m0 + 8) * OUTF + col]) =
                make_float2(c[2] + b0, c[3] + b1);
        }
    }
}

// ---------------------------------------------------------------------------
// Launch
// ---------------------------------------------------------------------------
extern "C" void kernel_launch(void* const* d_in, const int* in_sizes, int n_in,
                              void* d_out, int out_size) {
    const float* X      = (const float*)d_in[0];
    const float* nu_log = (const float*)d_in[1];
    const float* th_log = (const float*)d_in[2];
    const float* Bre    = (const float*)d_in[3];
    const float* Bim    = (const float*)d_in[4];
    const float* Cre    = (const float*)d_in[5];
    const float* Cim    = (const float*)d_in[6];
    const float* D      = (const float*)d_in[7];
    const float* bh_re  = (const float*)d_in[8];
    const float* bh_im  = (const float*)d_in[9];
    const float* bias   = (const float*)d_in[10];

    float* Y = (float*)d_out;
    float* out_hN = Y + Y_ELEMS;

    static int smem_set = 0;
    if (!smem_set) {
        cudaFuncSetAttribute(gemm1_kernel, cudaFuncAttributeMaxDynamicSharedMemorySize, SMEM_BYTES);
        cudaFuncSetAttribute(gemm2_kernel, cudaFuncAttributeMaxDynamicSharedMemorySize, SMEM_BYTES);
        smem_set = 1;
    }

    prep_kernel<<<1, HF>>>(nu_log, th_log, bh_re, bh_im);

    int wtot = 1024 * 256 + 256 * K2;
    wprep_kernel<<<(wtot + 255) / 256, 256>>>(Bre, Bim, Cre, Cim, D);

    convx_kernel<<<(MTOT * INF / 4 + 255) / 256, 256>>>(X);

    dim3 g1(8, MTOT / 128);
    gemm1_kernel<<<g1, 256, SMEM_BYTES>>>();

    scan_kernel<<<(BATCH * 16 * HF) / 256, 256>>>(out_hN);

    dim3 g2(2, MTOT / 128);
    gemm2_kernel<<<g2, 256, SMEM_BYTES>>>(bias, Y);
}